// round 1
// baseline (speedup 1.0000x reference)
#include <cuda_runtime.h>
#include <cuda_bf16.h>
#include <math.h>

#define OUT_G 12
#define V_G (OUT_G * OUT_G * OUT_G)   // 1728
#define MAXN 256

// Scratch (allocation-free rule: __device__ globals)
__device__ float g_roi_params[MAXN * 12];  // cx,cy,czc,cosa,sina,hx,hy,hz,vx,vy,vz,rad2
__device__ int   g_count[MAXN * V_G];

__device__ __forceinline__ unsigned enc_f(float f) {
    unsigned u = __float_as_uint(f);
    return (u & 0x80000000u) ? ~u : (u | 0x80000000u);
}
__device__ __forceinline__ float dec_f(unsigned u) {
    return (u & 0x80000000u) ? __uint_as_float(u & 0x7FFFFFFFu) : __uint_as_float(~u);
}

// ---------------------------------------------------------------------------
// Kernel 1: init output (zeros works for both modes: 0u == bits of 0.0f),
//           zero counts, precompute roi params.
// ---------------------------------------------------------------------------
__global__ void roi_init_kernel(const float* __restrict__ rois, float* __restrict__ out,
                                int N, long total_out) {
    long i = (long)blockIdx.x * blockDim.x + threadIdx.x;
    long stride = (long)gridDim.x * blockDim.x;
    for (long j = i; j < total_out; j += stride)
        out[j] = 0.0f;
    for (long j = i; j < (long)N * V_G; j += stride)
        g_count[j] = 0;
    if (i < N) {
        int r = (int)i;
        float cx = rois[7 * r + 0];
        float cy = rois[7 * r + 1];
        float czb = rois[7 * r + 2];
        float dx = rois[7 * r + 3];
        float dy = rois[7 * r + 4];
        float dz = rois[7 * r + 5];
        float rz = rois[7 * r + 6];
        float czc = czb + dz * 0.5f;
        float cosa = cosf(-rz);
        float sina = sinf(-rz);
        float hx = dx * 0.5f, hy = dy * 0.5f, hz = dz * 0.5f;
        float vx = dx / (float)OUT_G;
        float vy = dy / (float)OUT_G;
        float vz = dz / (float)OUT_G;
        float rad2 = hx * hx + hy * hy;
        float* R = &g_roi_params[r * 12];
        R[0] = cx; R[1] = cy; R[2] = czc; R[3] = cosa; R[4] = sina;
        R[5] = hx; R[6] = hy; R[7] = hz; R[8] = vx; R[9] = vy; R[10] = vz;
        R[11] = rad2;
    }
}

// ---------------------------------------------------------------------------
// Kernel 2: one thread per point, loop over rois (params in smem, broadcast).
// Early-outs: z-slab test, then xy bounding-radius test BEFORE the rotation.
// ---------------------------------------------------------------------------
__global__ void roi_points_kernel(const float* __restrict__ pts,
                                  const float* __restrict__ feat,
                                  const int* __restrict__ mode_p,
                                  float* __restrict__ out,
                                  int N, int P, int C) {
    __shared__ float s_roi[MAXN * 12];
    int nfl = N * 12;
    for (int i = threadIdx.x; i < nfl; i += blockDim.x)
        s_roi[i] = g_roi_params[i];
    __syncthreads();

    int mode = *mode_p;
    int p = blockIdx.x * blockDim.x + threadIdx.x;
    if (p >= P) return;

    float px = pts[3 * p + 0];
    float py = pts[3 * p + 1];
    float pz = pts[3 * p + 2];

    // feature registers loaded lazily on first hit
    float fv[32];
    bool loaded = false;

    for (int r = 0; r < N; r++) {
        const float* R = &s_roi[r * 12];
        float lz = pz - R[2];
        float hz = R[7];
        if (fabsf(lz) > hz) continue;                 // reference: |lz| <= dz/2
        float sx = px - R[0];
        float sy = py - R[1];
        float d2 = sx * sx + sy * sy;
        if (d2 > R[11]) continue;                     // xy bounding circle cull
        float cosa = R[3], sina = R[4];
        float lx = sx * cosa - sy * sina;
        float ly = sx * sina + sy * cosa;
        float hx = R[5], hy = R[6];
        if (fabsf(lx) >= hx) continue;                // reference: strict <
        if (fabsf(ly) >= hy) continue;

        // voxel index (match reference formula exactly: (l+h)/(d/OUT))
        int xi = (int)floorf((lx + hx) / R[8]);
        int yi = (int)floorf((ly + hy) / R[9]);
        int zi = (int)floorf((lz + hz) / R[10]);
        xi = min(max(xi, 0), OUT_G - 1);
        yi = min(max(yi, 0), OUT_G - 1);
        zi = min(max(zi, 0), OUT_G - 1);
        int vid = (xi * OUT_G + yi) * OUT_G + zi;
        int rv = r * V_G + vid;

        atomicAdd(&g_count[rv], 1);

        if (!loaded) {
            const float* fp = feat + (long)p * C;
            #pragma unroll 4
            for (int c = 0; c < C; c++) fv[c] = fp[c];
            loaded = true;
        }

        long base = (long)rv * C;
        if (mode == 0) {
            unsigned* o = reinterpret_cast<unsigned*>(out) + base;
            #pragma unroll 4
            for (int c = 0; c < C; c++)
                atomicMax(o + c, enc_f(fv[c]));
        } else {
            float* o = out + base;
            #pragma unroll 4
            for (int c = 0; c < C; c++)
                atomicAdd(o + c, fv[c]);
        }
    }
}

// ---------------------------------------------------------------------------
// Kernel 3: finalize. max: decode encoded uint, zero empty voxels.
//           avg: divide by max(count,1).
// ---------------------------------------------------------------------------
__global__ void roi_finalize_kernel(const int* __restrict__ mode_p,
                                    float* __restrict__ out,
                                    int C, long total_out) {
    long i = (long)blockIdx.x * blockDim.x + threadIdx.x;
    if (i >= total_out) return;
    int mode = *mode_p;
    long rv = i / C;
    int cnt = g_count[rv];
    if (mode == 0) {
        unsigned u = reinterpret_cast<unsigned*>(out)[i];
        out[i] = (cnt > 0) ? dec_f(u) : 0.0f;
    } else {
        out[i] = out[i] / fmaxf((float)cnt, 1.0f);
    }
}

extern "C" void kernel_launch(void* const* d_in, const int* in_sizes, int n_in,
                              void* d_out, int out_size) {
    const float* rois = (const float*)d_in[0];
    const float* pts = (const float*)d_in[1];
    const float* feat = (const float*)d_in[2];
    const int* mode_p = (const int*)d_in[3];
    float* out = (float*)d_out;

    int N = in_sizes[0] / 7;          // 64
    int P = in_sizes[1] / 3;          // 100000
    int C = in_sizes[2] / P;          // 16
    long total_out = (long)out_size;  // N*V*C

    {
        int threads = 256;
        long work = total_out;
        int blocks = (int)((work + threads - 1) / threads);
        if (blocks > 4096) blocks = 4096;
        roi_init_kernel<<<blocks, threads>>>(rois, out, N, total_out);
    }
    {
        int threads = 256;
        int blocks = (P + threads - 1) / threads;
        roi_points_kernel<<<blocks, threads>>>(pts, feat, mode_p, out, N, P, C);
    }
    {
        int threads = 256;
        int blocks = (int)((total_out + threads - 1) / threads);
        roi_finalize_kernel<<<blocks, threads>>>(mode_p, out, C, total_out);
    }
}

// round 6
// speedup vs baseline: 1.5312x; 1.5312x over previous
#include <cuda_runtime.h>
#include <cuda_bf16.h>
#include <math.h>

#define OUT_G 12
#define V_G (OUT_G * OUT_G * OUT_G)   // 1728
#define MAXN 256
#define NB 16                          // spatial bins per dim
#define NBINS (NB * NB * NB)           // 4096
#define NWMAX 4                        // mask words (up to 256 rois)
#define DOM_LO (-12.0f)
#define DOM_HI (12.0f)
#define CELL ((DOM_HI - DOM_LO) / (float)NB)   // 1.5

// Scratch (__device__ globals: allocation-free rule)
__device__ float g_roi[MAXN * 12];     // cx,cy,czc,cosa,sina,hx,hy,hz,vx,vy,vz,rad2
__device__ float g_aabb[MAXN * 6];     // xlo,xhi,ylo,yhi,zlo,zhi
__device__ int g_count[MAXN * V_G];
__device__ unsigned long long g_mask[NBINS * NWMAX];

__device__ __forceinline__ unsigned enc_f(float f) {
    unsigned u = __float_as_uint(f);
    return (u & 0x80000000u) ? ~u : (u | 0x80000000u);
}
__device__ __forceinline__ float dec_f(unsigned u) {
    return (u & 0x80000000u) ? __uint_as_float(u & 0x7FFFFFFFu) : __uint_as_float(~u);
}

// ---------------------------------------------------------------------------
// Kernel 1: per-roi params + AABB. Tiny (N threads).
// ---------------------------------------------------------------------------
__global__ void roi_params_kernel(const float* __restrict__ rois, int N) {
    int r = blockIdx.x * blockDim.x + threadIdx.x;
    if (r >= N) return;
    float cx = rois[7 * r + 0];
    float cy = rois[7 * r + 1];
    float czb = rois[7 * r + 2];
    float dx = rois[7 * r + 3];
    float dy = rois[7 * r + 4];
    float dz = rois[7 * r + 5];
    float rz = rois[7 * r + 6];
    float czc = czb + dz * 0.5f;
    float cosa = cosf(-rz);
    float sina = sinf(-rz);
    float hx = dx * 0.5f, hy = dy * 0.5f, hz = dz * 0.5f;
    float* R = &g_roi[r * 12];
    R[0] = cx; R[1] = cy; R[2] = czc; R[3] = cosa; R[4] = sina;
    R[5] = hx; R[6] = hy; R[7] = hz;
    R[8] = dx / (float)OUT_G; R[9] = dy / (float)OUT_G; R[10] = dz / (float)OUT_G;
    R[11] = hx * hx + hy * hy;
    // world-frame AABB of the rotated box (xy rotation only)
    float ex = fabsf(hx * cosa) + fabsf(hy * sina);
    float ey = fabsf(hx * sina) + fabsf(hy * cosa);
    float* A = &g_aabb[r * 6];
    A[0] = cx - ex; A[1] = cx + ex;
    A[2] = cy - ey; A[3] = cy + ey;
    A[4] = czc - hz; A[5] = czc + hz;
}

// ---------------------------------------------------------------------------
// Kernel 2: zero out (float4), zero counts, build bin->roi masks.
// Edge bins extend to +/-inf so clamped out-of-domain points stay correct.
// ---------------------------------------------------------------------------
__global__ void roi_setup_kernel(float* __restrict__ out, long total_out, int N) {
    int tid = blockIdx.x * blockDim.x + threadIdx.x;
    int nth = gridDim.x * blockDim.x;

    long nv4 = total_out >> 2;
    float4 z4 = make_float4(0.f, 0.f, 0.f, 0.f);
    float4* o4 = (float4*)out;
    for (long i = tid; i < nv4; i += nth) o4[i] = z4;
    for (long i = (nv4 << 2) + tid; i < total_out; i += nth) out[i] = 0.0f;

    long nc = (long)N * V_G;
    for (long i = tid; i < nc; i += nth) g_count[i] = 0;

    int nw = (N + 63) >> 6;
    for (int b = tid; b < NBINS; b += nth) {
        int bx = b % NB, by = (b / NB) % NB, bz = b / (NB * NB);
        float x0 = (bx == 0)      ? -3e38f : DOM_LO + bx * CELL;
        float x1 = (bx == NB - 1) ?  3e38f : DOM_LO + (bx + 1) * CELL;
        float y0 = (by == 0)      ? -3e38f : DOM_LO + by * CELL;
        float y1 = (by == NB - 1) ?  3e38f : DOM_LO + (by + 1) * CELL;
        float z0 = (bz == 0)      ? -3e38f : DOM_LO + bz * CELL;
        float z1 = (bz == NB - 1) ?  3e38f : DOM_LO + (bz + 1) * CELL;
        for (int w = 0; w < nw; w++) {
            unsigned long long m = 0ull;
            int rend = min(N, (w + 1) << 6);
            for (int r = (w << 6); r < rend; r++) {
                const float* A = &g_aabb[r * 6];
                bool ov = (A[0] <= x1) & (A[1] >= x0) &
                          (A[2] <= y1) & (A[3] >= y0) &
                          (A[4] <= z1) & (A[5] >= z0);
                if (ov) m |= 1ull << (r & 63);
            }
            g_mask[(long)b * NWMAX + w] = m;
        }
    }
}

// ---------------------------------------------------------------------------
// Kernel 3: one thread per point. Bin lookup -> exact test only on mask bits.
// ---------------------------------------------------------------------------
__global__ void roi_points_kernel(const float* __restrict__ pts,
                                  const float* __restrict__ feat,
                                  const int* __restrict__ mode_p,
                                  float* __restrict__ out,
                                  int N, int P, int C) {
    __shared__ float s_roi[MAXN * 12];
    int nfl = N * 12;
    for (int i = threadIdx.x; i < nfl; i += blockDim.x)
        s_roi[i] = g_roi[i];
    __syncthreads();

    int p = blockIdx.x * blockDim.x + threadIdx.x;
    if (p >= P) return;

    float px = pts[3 * p + 0];
    float py = pts[3 * p + 1];
    float pz = pts[3 * p + 2];

    const float invcell = 1.0f / CELL;
    int bx = min(NB - 1, max(0, (int)((px - DOM_LO) * invcell)));
    int by = min(NB - 1, max(0, (int)((py - DOM_LO) * invcell)));
    int bz = min(NB - 1, max(0, (int)((pz - DOM_LO) * invcell)));
    int bin = (bz * NB + by) * NB + bx;

    int nw = (N + 63) >> 6;
    int mode = *mode_p;

    for (int w = 0; w < nw; w++) {
        unsigned long long m = __ldg(&g_mask[(long)bin * NWMAX + w]);
        while (m) {
            int bit = __ffsll((long long)m) - 1;
            m &= m - 1;
            int r = (w << 6) + bit;
            const float* R = &s_roi[r * 12];

            float lz = pz - R[2];
            float hz = R[7];
            if (fabsf(lz) > hz) continue;
            float sx = px - R[0];
            float sy = py - R[1];
            if (sx * sx + sy * sy > R[11]) continue;
            float cosa = R[3], sina = R[4];
            float lx = sx * cosa - sy * sina;
            float ly = sx * sina + sy * cosa;
            float hx = R[5], hy = R[6];
            if (fabsf(lx) >= hx) continue;
            if (fabsf(ly) >= hy) continue;

            int xi = min(max((int)floorf((lx + hx) / R[8]), 0), OUT_G - 1);
            int yi = min(max((int)floorf((ly + hy) / R[9]), 0), OUT_G - 1);
            int zi = min(max((int)floorf((lz + hz) / R[10]), 0), OUT_G - 1);
            int rv = r * V_G + (xi * OUT_G + yi) * OUT_G + zi;

            atomicAdd(&g_count[rv], 1);
            long base = (long)rv * C;

            if ((C & 3) == 0) {
                const float4* fp4 = (const float4*)(feat + (long)p * C);
                if (mode == 0) {
                    unsigned* o = reinterpret_cast<unsigned*>(out) + base;
                    for (int c4 = 0; c4 < (C >> 2); c4++) {
                        float4 f = __ldg(fp4 + c4);
                        atomicMax(o + 4 * c4 + 0, enc_f(f.x));
                        atomicMax(o + 4 * c4 + 1, enc_f(f.y));
                        atomicMax(o + 4 * c4 + 2, enc_f(f.z));
                        atomicMax(o + 4 * c4 + 3, enc_f(f.w));
                    }
                } else {
                    float* o = out + base;
                    for (int c4 = 0; c4 < (C >> 2); c4++) {
                        float4 f = __ldg(fp4 + c4);
                        atomicAdd(o + 4 * c4 + 0, f.x);
                        atomicAdd(o + 4 * c4 + 1, f.y);
                        atomicAdd(o + 4 * c4 + 2, f.z);
                        atomicAdd(o + 4 * c4 + 3, f.w);
                    }
                }
            } else {
                const float* fp = feat + (long)p * C;
                if (mode == 0) {
                    unsigned* o = reinterpret_cast<unsigned*>(out) + base;
                    for (int c = 0; c < C; c++) atomicMax(o + c, enc_f(__ldg(fp + c)));
                } else {
                    float* o = out + base;
                    for (int c = 0; c < C; c++) atomicAdd(o + c, __ldg(fp + c));
                }
            }
        }
    }
}

// ---------------------------------------------------------------------------
// Kernel 4: finalize occupied voxels only. Empty voxels already hold 0.0f.
// ---------------------------------------------------------------------------
__global__ void roi_finalize_kernel(const int* __restrict__ mode_p,
                                    float* __restrict__ out,
                                    int C, int NV) {
    int v = blockIdx.x * blockDim.x + threadIdx.x;
    if (v >= NV) return;
    int cnt = g_count[v];
    if (cnt <= 0) return;   // init bits 0x0 decode to 0.0f for mode 0; avg of 0 stays 0
    int mode = *mode_p;
    long base = (long)v * C;
    if (mode == 0) {
        unsigned* o = reinterpret_cast<unsigned*>(out) + base;
        for (int c = 0; c < C; c++)
            o[c] = __float_as_uint(dec_f(o[c]));
    } else {
        float inv = 1.0f / (float)cnt;
        float* o = out + base;
        for (int c = 0; c < C; c++)
            o[c] *= inv;
    }
}

extern "C" void kernel_launch(void* const* d_in, const int* in_sizes, int n_in,
                              void* d_out, int out_size) {
    const float* rois = (const float*)d_in[0];
    const float* pts = (const float*)d_in[1];
    const float* feat = (const float*)d_in[2];
    const int* mode_p = (const int*)d_in[3];
    float* out = (float*)d_out;

    int N = in_sizes[0] / 7;          // 64
    int P = in_sizes[1] / 3;          // 100000
    int C = in_sizes[2] / P;          // 16
    long total_out = (long)out_size;  // N*V*C
    int NV = N * V_G;

    roi_params_kernel<<<(N + 255) / 256, 256>>>(rois, N);
    roi_setup_kernel<<<432, 256>>>(out, total_out, N);
    roi_points_kernel<<<(P + 255) / 256, 256>>>(pts, feat, mode_p, out, N, P, C);
    roi_finalize_kernel<<<(NV + 255) / 256, 256>>>(mode_p, out, C, NV);
}

// round 9
// speedup vs baseline: 1.5977x; 1.0434x over previous
#include <cuda_runtime.h>
#include <cuda_bf16.h>
#include <math.h>

#define OUT_G 12
#define V_G (OUT_G * OUT_G * OUT_G)   // 1728
#define MAXN 256
#define NB 16                          // spatial bins per dim
#define NBINS (NB * NB * NB)           // 4096
#define NWMAX 4                        // mask words (up to 256 rois)
#define DOM_LO (-12.0f)
#define DOM_HI (12.0f)
#define CELL ((DOM_HI - DOM_LO) / (float)NB)   // 1.5

// Scratch (__device__ globals: allocation-free rule)
__device__ float g_roi[MAXN * 12];     // cx,cy,czc,cosa,sina,hx,hy,hz,vx,vy,vz,rad2
__device__ float g_aabb[MAXN * 6];     // xlo,xhi,ylo,yhi,zlo,zhi
__device__ int g_count[MAXN * V_G];
__device__ unsigned long long g_mask[NBINS * NWMAX];

__device__ __forceinline__ unsigned enc_f(float f) {
    unsigned u = __float_as_uint(f);
    return (u & 0x80000000u) ? ~u : (u | 0x80000000u);
}
__device__ __forceinline__ float dec_f(unsigned u) {
    return (u & 0x80000000u) ? __uint_as_float(u & 0x7FFFFFFFu) : __uint_as_float(~u);
}

// ---------------------------------------------------------------------------
// Kernel 1: per-roi params + AABB. Tiny (N threads).
// ---------------------------------------------------------------------------
__global__ void roi_params_kernel(const float* __restrict__ rois, int N) {
    int r = blockIdx.x * blockDim.x + threadIdx.x;
    if (r >= N) return;
    float cx = rois[7 * r + 0];
    float cy = rois[7 * r + 1];
    float czb = rois[7 * r + 2];
    float dx = rois[7 * r + 3];
    float dy = rois[7 * r + 4];
    float dz = rois[7 * r + 5];
    float rz = rois[7 * r + 6];
    float czc = czb + dz * 0.5f;
    float cosa = cosf(-rz);
    float sina = sinf(-rz);
    float hx = dx * 0.5f, hy = dy * 0.5f, hz = dz * 0.5f;
    float* R = &g_roi[r * 12];
    R[0] = cx; R[1] = cy; R[2] = czc; R[3] = cosa; R[4] = sina;
    R[5] = hx; R[6] = hy; R[7] = hz;
    R[8] = dx / (float)OUT_G; R[9] = dy / (float)OUT_G; R[10] = dz / (float)OUT_G;
    R[11] = hx * hx + hy * hy;
    // world-frame AABB of the rotated box (xy rotation only)
    float ex = fabsf(hx * cosa) + fabsf(hy * sina);
    float ey = fabsf(hx * sina) + fabsf(hy * cosa);
    float* A = &g_aabb[r * 6];
    A[0] = cx - ex; A[1] = cx + ex;
    A[2] = cy - ey; A[3] = cy + ey;
    A[4] = czc - hz; A[5] = czc + hz;
}

// ---------------------------------------------------------------------------
// Kernel 2: zero out (float4), zero counts, build bin->roi masks.
// Edge bins extend to +/-inf so clamped out-of-domain points stay correct.
// ---------------------------------------------------------------------------
__global__ void roi_setup_kernel(float* __restrict__ out, long total_out, int N) {
    int tid = blockIdx.x * blockDim.x + threadIdx.x;
    int nth = gridDim.x * blockDim.x;

    long nv4 = total_out >> 2;
    float4 z4 = make_float4(0.f, 0.f, 0.f, 0.f);
    float4* o4 = (float4*)out;
    for (long i = tid; i < nv4; i += nth) o4[i] = z4;
    for (long i = (nv4 << 2) + tid; i < total_out; i += nth) out[i] = 0.0f;

    long nc = (long)N * V_G;
    for (long i = tid; i < nc; i += nth) g_count[i] = 0;

    int nw = (N + 63) >> 6;
    for (int b = tid; b < NBINS; b += nth) {
        int bx = b % NB, by = (b / NB) % NB, bz = b / (NB * NB);
        float x0 = (bx == 0)      ? -3e38f : DOM_LO + bx * CELL;
        float x1 = (bx == NB - 1) ?  3e38f : DOM_LO + (bx + 1) * CELL;
        float y0 = (by == 0)      ? -3e38f : DOM_LO + by * CELL;
        float y1 = (by == NB - 1) ?  3e38f : DOM_LO + (by + 1) * CELL;
        float z0 = (bz == 0)      ? -3e38f : DOM_LO + bz * CELL;
        float z1 = (bz == NB - 1) ?  3e38f : DOM_LO + (bz + 1) * CELL;
        for (int w = 0; w < nw; w++) {
            unsigned long long m = 0ull;
            int rend = min(N, (w + 1) << 6);
            for (int r = (w << 6); r < rend; r++) {
                const float* A = &g_aabb[r * 6];
                bool ov = (A[0] <= x1) & (A[1] >= x0) &
                          (A[2] <= y1) & (A[3] >= y0) &
                          (A[4] <= z1) & (A[5] >= z0);
                if (ov) m |= 1ull << (r & 63);
            }
            g_mask[(long)b * NWMAX + w] = m;
        }
    }
}

// ---------------------------------------------------------------------------
// Kernel 3: one thread per point. Bin lookup -> exact test only on mask bits.
// ---------------------------------------------------------------------------
__global__ void roi_points_kernel(const float* __restrict__ pts,
                                  const float* __restrict__ feat,
                                  const int* __restrict__ mode_p,
                                  float* __restrict__ out,
                                  int N, int P, int C) {
    __shared__ float s_roi[MAXN * 12];
    int nfl = N * 12;
    for (int i = threadIdx.x; i < nfl; i += blockDim.x)
        s_roi[i] = g_roi[i];
    __syncthreads();

    int p = blockIdx.x * blockDim.x + threadIdx.x;
    if (p >= P) return;

    float px = __ldg(&pts[3 * p + 0]);
    float py = __ldg(&pts[3 * p + 1]);
    float pz = __ldg(&pts[3 * p + 2]);

    const float invcell = 1.0f / CELL;
    int bx = min(NB - 1, max(0, (int)((px - DOM_LO) * invcell)));
    int by = min(NB - 1, max(0, (int)((py - DOM_LO) * invcell)));
    int bz = min(NB - 1, max(0, (int)((pz - DOM_LO) * invcell)));
    int bin = (bz * NB + by) * NB + bx;

    int nw = (N + 63) >> 6;
    int mode = __ldg(mode_p);

    for (int w = 0; w < nw; w++) {
        unsigned long long m = __ldg(&g_mask[(long)bin * NWMAX + w]);
        while (m) {
            int bit = __ffsll((long long)m) - 1;
            m &= m - 1;
            int r = (w << 6) + bit;
            const float* R = &s_roi[r * 12];

            float lz = pz - R[2];
            float hz = R[7];
            if (fabsf(lz) > hz) continue;
            float sx = px - R[0];
            float sy = py - R[1];
            if (sx * sx + sy * sy > R[11]) continue;
            float cosa = R[3], sina = R[4];
            float lx = sx * cosa - sy * sina;
            float ly = sx * sina + sy * cosa;
            float hx = R[5], hy = R[6];
            if (fabsf(lx) >= hx) continue;
            if (fabsf(ly) >= hy) continue;

            int xi = min(max((int)floorf((lx + hx) / R[8]), 0), OUT_G - 1);
            int yi = min(max((int)floorf((ly + hy) / R[9]), 0), OUT_G - 1);
            int zi = min(max((int)floorf((lz + hz) / R[10]), 0), OUT_G - 1);
            int rv = r * V_G + (xi * OUT_G + yi) * OUT_G + zi;

            atomicAdd(&g_count[rv], 1);
            long base = (long)rv * C;

            if ((C & 3) == 0) {
                const float4* fp4 = (const float4*)(feat + (long)p * C);
                if (mode == 0) {
                    unsigned* o = reinterpret_cast<unsigned*>(out) + base;
                    for (int c4 = 0; c4 < (C >> 2); c4++) {
                        float4 f = __ldg(fp4 + c4);
                        atomicMax(o + 4 * c4 + 0, enc_f(f.x));
                        atomicMax(o + 4 * c4 + 1, enc_f(f.y));
                        atomicMax(o + 4 * c4 + 2, enc_f(f.z));
                        atomicMax(o + 4 * c4 + 3, enc_f(f.w));
                    }
                } else {
                    float* o = out + base;
                    for (int c4 = 0; c4 < (C >> 2); c4++) {
                        float4 f = __ldg(fp4 + c4);
                        atomicAdd(o + 4 * c4 + 0, f.x);
                        atomicAdd(o + 4 * c4 + 1, f.y);
                        atomicAdd(o + 4 * c4 + 2, f.z);
                        atomicAdd(o + 4 * c4 + 3, f.w);
                    }
                }
            } else {
                const float* fp = feat + (long)p * C;
                if (mode == 0) {
                    unsigned* o = reinterpret_cast<unsigned*>(out) + base;
                    for (int c = 0; c < C; c++) atomicMax(o + c, enc_f(__ldg(fp + c)));
                } else {
                    float* o = out + base;
                    for (int c = 0; c < C; c++) atomicAdd(o + c, __ldg(fp + c));
                }
            }
        }
    }
}

// ---------------------------------------------------------------------------
// Kernel 4a: finalize, C divisible by 4: one thread per float4 (coalesced).
// c4pv = C/4 float4-chunks per voxel.
// ---------------------------------------------------------------------------
__global__ void roi_finalize_vec_kernel(const int* __restrict__ mode_p,
                                        float* __restrict__ out,
                                        int c4pv, int total4) {
    int i = blockIdx.x * blockDim.x + threadIdx.x;
    if (i >= total4) return;
    int v = i / c4pv;
    int cnt = __ldg(&g_count[v]);
    if (cnt <= 0) return;   // empty voxels already hold 0.0f (bits 0x0)
    int mode = __ldg(mode_p);
    float4* o4 = reinterpret_cast<float4*>(out) + i;
    float4 f = *o4;
    if (mode == 0) {
        f.x = dec_f(__float_as_uint(f.x));
        f.y = dec_f(__float_as_uint(f.y));
        f.z = dec_f(__float_as_uint(f.z));
        f.w = dec_f(__float_as_uint(f.w));
    } else {
        float inv = 1.0f / (float)cnt;
        f.x *= inv; f.y *= inv; f.z *= inv; f.w *= inv;
    }
    *o4 = f;
}

// ---------------------------------------------------------------------------
// Kernel 4b: generic finalize, one thread per element (coalesced).
// ---------------------------------------------------------------------------
__global__ void roi_finalize_gen_kernel(const int* __restrict__ mode_p,
                                        float* __restrict__ out,
                                        int C, long total) {
    long i = (long)blockIdx.x * blockDim.x + threadIdx.x;
    if (i >= total) return;
    int v = (int)(i / C);
    int cnt = __ldg(&g_count[v]);
    if (cnt <= 0) return;
    int mode = __ldg(mode_p);
    if (mode == 0) {
        unsigned u = reinterpret_cast<unsigned*>(out)[i];
        out[i] = dec_f(u);
    } else {
        out[i] = out[i] / (float)cnt;
    }
}

extern "C" void kernel_launch(void* const* d_in, const int* in_sizes, int n_in,
                              void* d_out, int out_size) {
    const float* rois = (const float*)d_in[0];
    const float* pts = (const float*)d_in[1];
    const float* feat = (const float*)d_in[2];
    const int* mode_p = (const int*)d_in[3];
    float* out = (float*)d_out;

    int N = in_sizes[0] / 7;          // 64
    int P = in_sizes[1] / 3;          // 100000
    int C = in_sizes[2] / P;          // 16
    long total_out = (long)out_size;  // N*V*C

    roi_params_kernel<<<(N + 255) / 256, 256>>>(rois, N);
    roi_setup_kernel<<<1024, 256>>>(out, total_out, N);
    roi_points_kernel<<<(P + 255) / 256, 256>>>(pts, feat, mode_p, out, N, P, C);

    if ((C & 3) == 0) {
        int c4pv = C >> 2;
        int total4 = (int)(total_out >> 2);
        roi_finalize_vec_kernel<<<(total4 + 255) / 256, 256>>>(mode_p, out, c4pv, total4);
    } else {
        roi_finalize_gen_kernel<<<(int)((total_out + 255) / 256), 256>>>(mode_p, out, C, total_out);
    }
}